// round 6
// baseline (speedup 1.0000x reference)
#include <cuda_runtime.h>
#include <math.h>

#define NT 512
#define NFEAT 1024
#define NCAT 1536
#define MEMSZ 16384
#define RSQRTNF 0.17677669529663689f

// ---- output layout (float element offsets) ----
#define OUT_MEM    0
#define OUT_TMEM   8388608
#define OUT_FMEM   8404992
#define OUT_ARE    25182208
#define OUT_AIM    25198592
#define OUT_FREQ   25214976
#define OUT_RP     25215008
#define OUT_BIAS   26001440
#define OUT_FMEAN  26001952
#define OUT_AGRE   26002976
#define OUT_AGIM   26019360
#define OUT_FG     26035744
#define OUT_RPG    26035776

// ---- scratch ----
__device__ __align__(16) float g_ux[32 * NFEAT];
__device__ __align__(16) float g_uz[16 * NT];
__device__ __align__(16) float g_zbm[32 * NT];
__device__ __align__(16) float g_G[16 * NT];
__device__ __align__(16) float g_D[16 * NT];
__device__ __align__(16) float g_ct[16 * 32];
__device__ __align__(16) float g_st[16 * 32];
__device__ __align__(16) float g_tp2[32];
__device__ __align__(16) float g_dfr[2][32];
__device__ __align__(16) float g_agre[32 * NT];
__device__ __align__(16) float g_agim[32 * NT];
__device__ __align__(16) float g_fga[2][32];
__device__ __align__(16) float g_rg[NCAT * NT];
__device__ float g_nrm[2][4];
__device__ float g_lr;

__device__ __forceinline__ float sgnf(float v) {
    return (v > 0.f) ? 1.f : ((v < 0.f) ? -1.f : 0.f);
}

__device__ __forceinline__ void trig_one(float fq_f, float cfv, float tt,
                                         float* cv, float* sv, float* dfr) {
    double fq = (double)fq_f;
    double th = tanh(fq);
    double w = (double)cfv + 2.0 * th;
    double sg = 1.0 / (1.0 + exp(-w));
    double ph = (double)tt * (sg * 0.5);
    *cv = (float)cos(ph);
    *sv = (float)sin(ph);
    *dfr = (float)(0.5 * sg * (1.0 - sg) * 2.0 * (1.0 - th * th));
}

// ================= side stream: big copies with inline row substitution =================
__global__ void k_bigcopy(const float* __restrict__ memory, const float* __restrict__ fmem,
                          const int* __restrict__ tmem,
                          const float* __restrict__ z, const float* __restrict__ x,
                          const int* __restrict__ tp, const int* __restrict__ dsp,
                          float* __restrict__ out) {
    const long long N1 = (long long)MEMSZ * NT / 4;
    const long long N2c = (long long)MEMSZ * NFEAT / 4;
    const long long N3c = MEMSZ / 4;
    long long u = (long long)blockIdx.x * 256 + threadIdx.x;
    int ds = *dsp;
    if (u < N1) {
        int k = (int)u;
        int row = (k * 4) >> 9;
        float4 v;
        if (row == ds) v = *(const float4*)(z + ((k * 4) & 511));
        else           v = ((const float4*)memory)[k];
        ((float4*)(out + OUT_MEM))[k] = v;
    } else if (u < N1 + N2c) {
        int k = (int)(u - N1);
        int row = (k * 4) >> 10;
        float4 v;
        if (row == ds) v = *(const float4*)(x + ((k * 4) & 1023));
        else           v = ((const float4*)fmem)[k];
        ((float4*)(out + OUT_FMEM))[k] = v;
    } else if (u < N1 + N2c + N3c) {
        int k = (int)(u - N1 - N2c);
        int4 iv = ((const int4*)tmem)[k];
        float4 f = make_float4((float)iv.x, (float)iv.y, (float)iv.z, (float)iv.w);
        if ((ds >> 2) == k) ((float*)&f)[ds & 3] = (float)(*tp);
        ((float4*)(out + OUT_TMEM))[k] = f;
    }
}

// ================= front: gather + batch-0 eval + bias/fmean + zero accums =================
__global__ void k_front(const int* __restrict__ ts, const float* __restrict__ memory,
                        const float* __restrict__ fmem, const int* __restrict__ tmem,
                        const float* __restrict__ z, const float* __restrict__ x,
                        const float* __restrict__ fmean, const float* __restrict__ bias,
                        const int* __restrict__ tp, const int* __restrict__ dsp,
                        const float* __restrict__ freq_in, const float* __restrict__ cf,
                        const float* __restrict__ are_in, const float* __restrict__ aim_in,
                        float* __restrict__ out) {
    int bid = blockIdx.x, tid = threadIdx.x;  // 512 threads
    int ds = *dsp;
    float dsn = (float)(ds + 1);
    if (bid < 32) {
        int s = bid;
        int idx = ts[s];
        g_zbm[s * NT + tid] = (idx == ds) ? z[tid] : memory[idx * NT + tid];
        for (int jj = tid; jj < NFEAT; jj += 512) {
            float xv = (idx == ds) ? x[jj] : fmem[idx * NFEAT + jj];
            float fm = (fmean[jj] * dsn + x[jj]) / (dsn + 1.0f);
            g_ux[s * NFEAT + jj] = xv - fm;
        }
        if (tid == 0) {
            float tv = (idx == ds) ? (float)(*tp) : (float)tmem[idx];
            g_tp2[s] = 6.2831853071795864769f * tv;
        }
    } else if (bid < 48) {
        // batch-0 eval for sample i, entirely from INPUT params
        __shared__ float sc[32], ss[32];
        int i = bid - 32;
        int idx = ts[i];
        float tv = (idx == ds) ? (float)(*tp) : (float)tmem[idx];
        float tt = 6.2831853071795864769f * tv;
        if (tid < 32) {
            float cv, sv, dfr;
            trig_one(freq_in[tid], cf[tid], tt, &cv, &sv, &dfr);
            sc[tid] = cv; ss[tid] = sv;
            g_ct[i * 32 + tid] = cv;
            g_st[i * 32 + tid] = sv;
            if (i == 0) g_dfr[0][tid] = dfr;
        }
        __syncthreads();
        float acc = 0.f;
#pragma unroll
        for (int f = 0; f < 32; f++)
            acc += sc[f] * are_in[f * NT + tid] - ss[f] * aim_in[f * NT + tid];
        g_uz[i * NT + tid] = acc * RSQRTNF;
    } else if (bid == 48) {
        out[OUT_BIAS + tid] = (bias[tid] * dsn + z[tid]) / (dsn + 1.0f);
    } else {
        for (int u = tid; u < NFEAT; u += 512)
            out[OUT_FMEAN + u] = (fmean[u] * dsn + x[u]) / (dsn + 1.0f);
        if (tid < 8) ((float*)g_nrm)[tid] = 0.f;
        if (tid >= 32 && tid < 96) ((float*)g_fga)[tid - 32] = 0.f;
        if (tid == 100) g_lr = (float)pow(0.977, (double)(ds + 1));
    }
}

// ================= N2: [eval b1] + full r + G/D  (64 blocks x 256) =================
__global__ void k_N2(int b, int do_eval,
                     const float* __restrict__ freq_p, const float* __restrict__ cf,
                     const float* __restrict__ are_p, const float* __restrict__ aim_p,
                     const float* __restrict__ rp_p,
                     const float* __restrict__ bias_p, const float* __restrict__ z_p,
                     const int* __restrict__ dsp) {
    __shared__ float smu[NCAT];
    __shared__ float red[8][32][4];
    __shared__ float sc[32], ss[32];
    int tid = threadIdx.x;
    int i = blockIdx.x >> 2, tq = blockIdx.x & 3;
    for (int k = tid; k < NFEAT; k += 256)
        smu[k] = g_ux[(b * 16 + i) * NFEAT + k];
    if (do_eval) {
        if (tid < 32) {
            float cv, sv, dfr;
            trig_one(freq_p[tid], cf[tid], g_tp2[16 + i], &cv, &sv, &dfr);
            sc[tid] = cv; ss[tid] = sv;
            if (tq == 0) {
                g_ct[i * 32 + tid] = cv;
                g_st[i * 32 + tid] = sv;
            }
            if (blockIdx.x == 0) g_dfr[1][tid] = dfr;
        }
        __syncthreads();
        for (int t2 = tid; t2 < NT; t2 += 256) {
            float acc = 0.f;
#pragma unroll
            for (int f = 0; f < 32; f++)
                acc += sc[f] * are_p[f * NT + t2] - ss[f] * aim_p[f * NT + t2];
            acc *= RSQRTNF;
            smu[NFEAT + t2] = acc;
            if (tq == 0) g_uz[i * NT + t2] = acc;
        }
    } else {
        for (int t2 = tid; t2 < NT; t2 += 256)
            smu[NFEAT + t2] = g_uz[i * NT + t2];
    }
    __syncthreads();
    {
        int q = tid & 31, js = tid >> 5;
        int tb = tq * 128 + q * 4;
        float a0 = 0.f, a1 = 0.f, a2 = 0.f, a3 = 0.f;
        const float* rpb = rp_p + tb;
        int j0 = js * 192;
#pragma unroll 8
        for (int j = j0; j < j0 + 192; j++) {
            float uv = smu[j];
            float4 rv = *(const float4*)(rpb + (size_t)j * NT);
            a0 += uv * rv.x; a1 += uv * rv.y; a2 += uv * rv.z; a3 += uv * rv.w;
        }
        red[js][q][0] = a0; red[js][q][1] = a1; red[js][q][2] = a2; red[js][q][3] = a3;
    }
    __syncthreads();
    if (tid < 128) {
        int qq = tid >> 2, c = tid & 3;
        float rt = 0.f;
#pragma unroll
        for (int k = 0; k < 8; k++) rt += red[k][qq][c];
        int t = tq * 128 + qq * 4 + c;
        int ds = *dsp;
        float dsn = (float)(ds + 1);
        float bv = (bias_p[t] * dsn + z_p[t]) / (dsn + 1.0f);
        float zh = smu[NFEAT + t] + bv;
        float zb = g_zbm[(b * 16 + i) * NT + t];
        float ar = fabsf(rt) + 1.0f;
        float z2 = zh + rt / ar;
        g_G[i * NT + t] = (-0.03f / 16.0f) * sgnf(zb - z2) / (ar * ar);
        g_D[i * NT + t] = (-1.0f / 16.0f) * sgnf(zb - zh);
    }
}

// ================= N3: backD+ampgrad (128 blocks x 4t, G in smem) | rg (96 blocks x 16j) =================
__global__ void k_N3(int b, const float* __restrict__ rp_p,
                     const float* __restrict__ are_p, const float* __restrict__ aim_p) {
    __shared__ float sbuf[9872];
    int bid = blockIdx.x, tid = threadIdx.x;  // 512 threads
    if (bid < 128) {
        const int TPB = 4;
        int t0 = bid * TPB;
        float* sG   = sbuf;          // 8192
        float* srz  = sbuf + 8192;   // 512
        float* sct  = sbuf + 8704;   // 512
        float* sst  = sbuf + 9216;   // 512... (overlaps? 8704+512=9216 ok; 9216+512=9728)
        float* sD   = sbuf + 9728;   // 64
        float* stt  = sbuf + 9792;   // 16
        float* sfga = sbuf + 9808;   // 32
        float* sred = sbuf + 9840;   // 16
        for (int k = tid; k < 8192; k += 512) sG[k] = g_G[k];
        sct[tid] = g_ct[tid];
        sst[tid] = g_st[tid];
        if (tid < 16) stt[tid] = g_tp2[b * 16 + tid];
        if (tid < 32) sfga[tid] = 0.f;
        int lane = tid & 31, w = tid >> 5;
        for (int tt = 0; tt < TPB; tt++) {
            __syncthreads();
            srz[tid] = rp_p[(size_t)(NFEAT + t0 + tt) * NT + tid];
            __syncthreads();
            float acc = 0.f;
#pragma unroll 4
            for (int tq = lane; tq < NT; tq += 32)
                acc += sG[w * NT + tq] * srz[tq];
#pragma unroll
            for (int o = 16; o > 0; o >>= 1)
                acc += __shfl_down_sync(0xffffffffu, acc, o);
            if (lane == 0) sD[tt * 16 + w] = g_D[w * NT + t0 + tt] + acc;
        }
        __syncthreads();
        float nrm = 0.f;
        if (tid < TPB * 32) {
            int tt = tid >> 5, f = tid & 31;
            int t = t0 + tt;
            float are = are_p[f * NT + t], aim = aim_p[f * NT + t];
            float sre = 0.f, sim = 0.f, sf = 0.f;
#pragma unroll
            for (int i = 0; i < 16; i++) {
                float d = sD[tt * 16 + i];
                float c = sct[i * 32 + f];
                float s = sst[i * 32 + f];
                sre += d * c;
                sim -= d * s;
                sf += d * (-s * are - c * aim) * stt[i];
            }
            float aa = sqrtf(are * are + aim * aim);
            float reg = 0.01f / (2.0f * aa * sqrtf(aa));
            float agre = sre * RSQRTNF + are * reg;
            float agim = sim * RSQRTNF + aim * reg;
            g_agre[f * NT + t] = agre;
            g_agim[f * NT + t] = agim;
            atomicAdd(&sfga[f], sf);
            nrm = agre * agre + agim * agim;
        }
#pragma unroll
        for (int o = 16; o > 0; o >>= 1)
            nrm += __shfl_down_sync(0xffffffffu, nrm, o);
        if ((tid & 31) == 0) sred[tid >> 5] = nrm;
        __syncthreads();
        if (tid == 0) {
            float s = 0.f;
#pragma unroll
            for (int k = 0; k < 16; k++) s += sred[k];
            atomicAdd(&g_nrm[b][0], s);
        }
        if (tid < 32) atomicAdd(&g_fga[b][tid], sfga[tid]);
    } else {
        float* su   = sbuf;          // 256
        float* sred = sbuf + 256;    // 16
        int j0 = (bid - 128) * 16;
        if (tid < 256) {
            int i = tid >> 4, jj = tid & 15;
            int j = j0 + jj;
            su[tid] = (j < NFEAT) ? g_ux[(b * 16 + i) * NFEAT + j]
                                  : g_uz[i * NT + (j - NFEAT)];
        }
        __syncthreads();
        float gv[16];
#pragma unroll
        for (int i = 0; i < 16; i++) gv[i] = g_G[i * NT + tid];
        float loc = 0.f;
#pragma unroll
        for (int jj = 0; jj < 16; jj++) {
            float acc = 0.f;
#pragma unroll
            for (int i = 0; i < 16; i++) acc += su[i * 16 + jj] * gv[i];
            g_rg[(j0 + jj) * NT + tid] = acc;
            loc += acc * acc;
        }
#pragma unroll
        for (int o = 16; o > 0; o >>= 1)
            loc += __shfl_down_sync(0xffffffffu, loc, o);
        if ((tid & 31) == 0) sred[tid >> 5] = loc;
        __syncthreads();
        if (tid == 0) {
            float s = 0.f;
#pragma unroll
            for (int k = 0; k < 16; k++) s += sred[k];
            atomicAdd(&g_nrm[b][2], s);
        }
    }
}

// ================= update: momentum + SGD, src -> out (no pre-copy needed) =================
__global__ void k_update(int b,
                         const float* __restrict__ rpg_s, const float* __restrict__ rp_s,
                         const float* __restrict__ agre_s, const float* __restrict__ are_s,
                         const float* __restrict__ agim_s, const float* __restrict__ aim_s,
                         const float* __restrict__ fg_s, const float* __restrict__ freq_s,
                         float* __restrict__ out) {
    const int NRP4 = NCAT * NT / 4;   // 196608
    const int NAMP4 = 32 * NT / 4;    // 4096
    int idx = blockIdx.x * 256 + threadIdx.x;
    float lr = g_lr;
    if (idx < NRP4) {
        float rn = sqrtf(g_nrm[b][2]) + 1.0f;
        float4 mo = ((const float4*)rpg_s)[idx];
        float4 gr = ((const float4*)g_rg)[idx];
        float4 pv = ((const float4*)rp_s)[idx];
        mo.x = mo.x * 0.85f + gr.x / rn;  pv.x -= mo.x * lr;
        mo.y = mo.y * 0.85f + gr.y / rn;  pv.y -= mo.y * lr;
        mo.z = mo.z * 0.85f + gr.z / rn;  pv.z -= mo.z * lr;
        mo.w = mo.w * 0.85f + gr.w / rn;  pv.w -= mo.w * lr;
        ((float4*)(out + OUT_RPG))[idx] = mo;
        ((float4*)(out + OUT_RP))[idx] = pv;
    } else if (idx < NRP4 + NAMP4) {
        int k = idx - NRP4;
        float an = sqrtf(g_nrm[b][0]) + 1.0f;
        float4 mo = ((const float4*)agre_s)[k];
        float4 gr = ((const float4*)g_agre)[k];
        float4 pv = ((const float4*)are_s)[k];
        mo.x = mo.x * 0.85f + gr.x / an;  pv.x -= mo.x * lr;
        mo.y = mo.y * 0.85f + gr.y / an;  pv.y -= mo.y * lr;
        mo.z = mo.z * 0.85f + gr.z / an;  pv.z -= mo.z * lr;
        mo.w = mo.w * 0.85f + gr.w / an;  pv.w -= mo.w * lr;
        ((float4*)(out + OUT_AGRE))[k] = mo;
        ((float4*)(out + OUT_ARE))[k] = pv;
        float4 mi = ((const float4*)agim_s)[k];
        float4 gi = ((const float4*)g_agim)[k];
        float4 pi = ((const float4*)aim_s)[k];
        mi.x = mi.x * 0.85f + gi.x / an;  pi.x -= mi.x * lr;
        mi.y = mi.y * 0.85f + gi.y / an;  pi.y -= mi.y * lr;
        mi.z = mi.z * 0.85f + gi.z / an;  pi.z -= mi.z * lr;
        mi.w = mi.w * 0.85f + gi.w / an;  pi.w -= mi.w * lr;
        ((float4*)(out + OUT_AGIM))[k] = mi;
        ((float4*)(out + OUT_AIM))[k] = pi;
    }
    if (blockIdx.x == 0 && threadIdx.x < 32) {
        int f = threadIdx.x;
        float fgv = (g_fga[b][f] * RSQRTNF) * g_dfr[b][f];
        float n = fgv * fgv;
#pragma unroll
        for (int o = 16; o > 0; o >>= 1)
            n += __shfl_xor_sync(0xffffffffu, n, o);
        float fn = sqrtf(n) + 1.0f;
        float m = fg_s[f] * 0.85f + fgv / fn;
        out[OUT_FG + f] = m;
        out[OUT_FREQ + f] = freq_s[f] - m * lr;
    }
}

extern "C" void kernel_launch(void* const* d_in, const int* in_sizes, int n_in,
                              void* d_out, int out_size) {
    const int*   t_p    = (const int*)d_in[0];
    const int*   ds_p   = (const int*)d_in[1];
    const int*   ts     = (const int*)d_in[2];
    const float* x      = (const float*)d_in[3];
    const float* z      = (const float*)d_in[4];
    const float* memory = (const float*)d_in[5];
    const int*   tmem   = (const int*)d_in[6];
    const float* fmem   = (const float*)d_in[7];
    const float* amp_re = (const float*)d_in[8];
    const float* amp_im = (const float*)d_in[9];
    const float* freq   = (const float*)d_in[10];
    const float* cfreq  = (const float*)d_in[11];
    const float* rp     = (const float*)d_in[12];
    const float* fmean  = (const float*)d_in[13];
    const float* bias   = (const float*)d_in[14];
    const float* agre   = (const float*)d_in[15];
    const float* agim   = (const float*)d_in[16];
    const float* fg     = (const float*)d_in[17];
    const float* rpg    = (const float*)d_in[18];
    float* out = (float*)d_out;

    static cudaStream_t s1 = 0;
    static cudaEvent_t e0 = 0, e1 = 0;
    if (!s1) {
        cudaStreamCreateWithFlags(&s1, cudaStreamNonBlocking);
        cudaEventCreateWithFlags(&e0, cudaEventDisableTiming);
        cudaEventCreateWithFlags(&e1, cudaEventDisableTiming);
    }

    // ---- fork: big copies on side stream ----
    cudaEventRecord(e0, 0);
    cudaStreamWaitEvent(s1, e0, 0);
    {
        const long long total4 = (long long)MEMSZ * NT / 4 + (long long)MEMSZ * NFEAT / 4 + MEMSZ / 4;
        int blocks = (int)((total4 + 255) / 256);
        k_bigcopy<<<blocks, 256, 0, s1>>>(memory, fmem, tmem, z, x, t_p, ds_p, out);
    }
    cudaEventRecord(e1, s1);

    // ---- main chain: 7 light nodes ----
    k_front<<<50, 512>>>(ts, memory, fmem, tmem, z, x, fmean, bias,
                         t_p, ds_p, freq, cfreq, amp_re, amp_im, out);

    // batch 0: everything reads INPUT params, update writes out
    k_N2<<<64, 256>>>(0, 0, freq, cfreq, amp_re, amp_im, rp, bias, z, ds_p);
    k_N3<<<224, 512>>>(0, rp, amp_re, amp_im);
    k_update<<<(NCAT * NT / 4 + 32 * NT / 4) / 256, 256>>>(0, rpg, rp, agre, amp_re,
                                                           agim, amp_im, fg, freq, out);

    // batch 1: params from out (updated), in place
    k_N2<<<64, 256>>>(1, 1, out + OUT_FREQ, cfreq, out + OUT_ARE, out + OUT_AIM,
                      out + OUT_RP, bias, z, ds_p);
    k_N3<<<224, 512>>>(1, out + OUT_RP, out + OUT_ARE, out + OUT_AIM);
    k_update<<<(NCAT * NT / 4 + 32 * NT / 4) / 256, 256>>>(1, out + OUT_RPG, out + OUT_RP,
                                                           out + OUT_AGRE, out + OUT_ARE,
                                                           out + OUT_AGIM, out + OUT_AIM,
                                                           out + OUT_FG, out + OUT_FREQ, out);

    // ---- join ----
    cudaStreamWaitEvent(0, e1, 0);
    (void)in_sizes; (void)n_in; (void)out_size;
}

// round 7
// speedup vs baseline: 1.0651x; 1.0651x over previous
#include <cuda_runtime.h>
#include <math.h>

#define NT 512
#define NFEAT 1024
#define NCAT 1536
#define MEMSZ 16384
#define RSQRTNF 0.17677669529663689f

// ---- output layout (float element offsets) ----
#define OUT_MEM    0
#define OUT_TMEM   8388608
#define OUT_FMEM   8404992
#define OUT_ARE    25182208
#define OUT_AIM    25198592
#define OUT_FREQ   25214976
#define OUT_RP     25215008
#define OUT_BIAS   26001440
#define OUT_FMEAN  26001952
#define OUT_AGRE   26002976
#define OUT_AGIM   26019360
#define OUT_FG     26035744
#define OUT_RPG    26035776

// ---- scratch ----
__device__ __align__(16) float g_ux[32 * NFEAT];   // x-part of u, all 32 samples
__device__ __align__(16) float g_uz[16 * NT];      // z-part of u, current batch
__device__ __align__(16) float g_zbm[32 * NT];
__device__ __align__(16) float g_G[16 * NT];
__device__ __align__(16) float g_D[16 * NT];
__device__ __align__(16) float g_ct[16 * 32];
__device__ __align__(16) float g_st[16 * 32];
__device__ __align__(16) float g_tp2[32];
__device__ __align__(16) float g_dfr[2][32];
__device__ __align__(16) float g_agre[32 * NT];
__device__ __align__(16) float g_agim[32 * NT];
__device__ __align__(16) float g_fga[2][32];
__device__ __align__(16) float g_rg[NCAT * NT];
__device__ float g_nrm[2][4];
__device__ float g_lr;

__device__ __forceinline__ float sgnf(float v) {
    return (v > 0.f) ? 1.f : ((v < 0.f) ? -1.f : 0.f);
}

__device__ __forceinline__ void trig_one(float fq_f, float cfv, float tt,
                                         float* cv, float* sv, float* dfr) {
    double fq = (double)fq_f;
    double th = tanh(fq);
    double w = (double)cfv + 2.0 * th;
    double sg = 1.0 / (1.0 + exp(-w));
    double ph = (double)tt * (sg * 0.5);
    *cv = (float)cos(ph);
    *sv = (float)sin(ph);
    *dfr = (float)(0.5 * sg * (1.0 - sg) * 2.0 * (1.0 - th * th));
}

// ================= side stream: big copies with inline row substitution =================
__global__ void k_bigcopy(const float* __restrict__ memory, const float* __restrict__ fmem,
                          const int* __restrict__ tmem,
                          const float* __restrict__ z, const float* __restrict__ x,
                          const int* __restrict__ tp, const int* __restrict__ dsp,
                          float* __restrict__ out) {
    const long long N1 = (long long)MEMSZ * NT / 4;
    const long long N2c = (long long)MEMSZ * NFEAT / 4;
    const long long N3c = MEMSZ / 4;
    long long u = (long long)blockIdx.x * 256 + threadIdx.x;
    int ds = *dsp;
    if (u < N1) {
        int k = (int)u;
        int row = (k * 4) >> 9;
        float4 v;
        if (row == ds) v = *(const float4*)(z + ((k * 4) & 511));
        else           v = ((const float4*)memory)[k];
        ((float4*)(out + OUT_MEM))[k] = v;
    } else if (u < N1 + N2c) {
        int k = (int)(u - N1);
        int row = (k * 4) >> 10;
        float4 v;
        if (row == ds) v = *(const float4*)(x + ((k * 4) & 1023));
        else           v = ((const float4*)fmem)[k];
        ((float4*)(out + OUT_FMEM))[k] = v;
    } else if (u < N1 + N2c + N3c) {
        int k = (int)(u - N1 - N2c);
        int4 iv = ((const int4*)tmem)[k];
        float4 f = make_float4((float)iv.x, (float)iv.y, (float)iv.z, (float)iv.w);
        if ((ds >> 2) == k) ((float*)&f)[ds & 3] = (float)(*tp);
        ((float4*)(out + OUT_TMEM))[k] = f;
    }
}

// ================= front: gather + batch-0 eval + bias/fmean + zero accums =================
__global__ void k_front(const int* __restrict__ ts, const float* __restrict__ memory,
                        const float* __restrict__ fmem, const int* __restrict__ tmem,
                        const float* __restrict__ z, const float* __restrict__ x,
                        const float* __restrict__ fmean, const float* __restrict__ bias,
                        const int* __restrict__ tp, const int* __restrict__ dsp,
                        const float* __restrict__ freq_in, const float* __restrict__ cf,
                        const float* __restrict__ are_in, const float* __restrict__ aim_in,
                        float* __restrict__ out) {
    int bid = blockIdx.x, tid = threadIdx.x;  // 512 threads
    int ds = *dsp;
    float dsn = (float)(ds + 1);
    if (bid < 32) {
        int s = bid;
        int idx = ts[s];
        g_zbm[s * NT + tid] = (idx == ds) ? z[tid] : memory[idx * NT + tid];
        for (int jj = tid; jj < NFEAT; jj += 512) {
            float xv = (idx == ds) ? x[jj] : fmem[idx * NFEAT + jj];
            float fm = (fmean[jj] * dsn + x[jj]) / (dsn + 1.0f);
            g_ux[s * NFEAT + jj] = xv - fm;
        }
        if (tid == 0) {
            float tv = (idx == ds) ? (float)(*tp) : (float)tmem[idx];
            g_tp2[s] = 6.2831853071795864769f * tv;
        }
    } else if (bid < 48) {
        // batch-0 eval for sample i, entirely from INPUT params
        __shared__ float sc[32], ss[32];
        int i = bid - 32;
        int idx = ts[i];
        float tv = (idx == ds) ? (float)(*tp) : (float)tmem[idx];
        float tt = 6.2831853071795864769f * tv;
        if (tid < 32) {
            float cv, sv, dfr;
            trig_one(freq_in[tid], cf[tid], tt, &cv, &sv, &dfr);
            sc[tid] = cv; ss[tid] = sv;
            g_ct[i * 32 + tid] = cv;
            g_st[i * 32 + tid] = sv;
            if (i == 0) g_dfr[0][tid] = dfr;
        }
        __syncthreads();
        float acc = 0.f;
#pragma unroll
        for (int f = 0; f < 32; f++)
            acc += sc[f] * are_in[f * NT + tid] - ss[f] * aim_in[f * NT + tid];
        g_uz[i * NT + tid] = acc * RSQRTNF;
    } else if (bid == 48) {
        out[OUT_BIAS + tid] = (bias[tid] * dsn + z[tid]) / (dsn + 1.0f);
    } else {
        for (int u = tid; u < NFEAT; u += 512)
            out[OUT_FMEAN + u] = (fmean[u] * dsn + x[u]) / (dsn + 1.0f);
        if (tid < 8) ((float*)g_nrm)[tid] = 0.f;
        if (tid >= 32 && tid < 96) ((float*)g_fga)[tid - 32] = 0.f;
        if (tid == 100) g_lr = (float)pow(0.977, (double)(ds + 1));
    }
}

// ================= N2: [eval b1] + full r + G/D  (64 blocks x 256)  [R4 body] =================
__global__ void k_N2(int b, int do_eval,
                     const float* __restrict__ freq_p, const float* __restrict__ cf,
                     const float* __restrict__ are_p, const float* __restrict__ aim_p,
                     const float* __restrict__ rp_p,
                     const float* __restrict__ bias_p, const float* __restrict__ z_p,
                     const int* __restrict__ dsp) {
    __shared__ float smu[NCAT];
    __shared__ float red[8][32][4];
    __shared__ float sc[32], ss[32];
    int tid = threadIdx.x;
    int i = blockIdx.x >> 2, tq = blockIdx.x & 3;
    for (int k = tid; k < NFEAT; k += 256)
        smu[k] = g_ux[(b * 16 + i) * NFEAT + k];
    if (do_eval) {
        if (tid < 32) {
            float cv, sv, dfr;
            trig_one(freq_p[tid], cf[tid], g_tp2[16 + i], &cv, &sv, &dfr);
            sc[tid] = cv; ss[tid] = sv;
            if (tq == 0) {
                g_ct[i * 32 + tid] = cv;
                g_st[i * 32 + tid] = sv;
            }
            if (blockIdx.x == 0) g_dfr[1][tid] = dfr;
        }
        __syncthreads();
        for (int t2 = tid; t2 < NT; t2 += 256) {
            float acc = 0.f;
#pragma unroll
            for (int f = 0; f < 32; f++)
                acc += sc[f] * are_p[f * NT + t2] - ss[f] * aim_p[f * NT + t2];
            acc *= RSQRTNF;
            smu[NFEAT + t2] = acc;
            if (tq == 0) g_uz[i * NT + t2] = acc;
        }
    } else {
        for (int t2 = tid; t2 < NT; t2 += 256)
            smu[NFEAT + t2] = g_uz[i * NT + t2];
    }
    __syncthreads();
    {
        int q = tid & 31, js = tid >> 5;
        int tb = tq * 128 + q * 4;
        float a0 = 0.f, a1 = 0.f, a2 = 0.f, a3 = 0.f;
        const float* rpb = rp_p + tb;
        int j0 = js * 192;
#pragma unroll 8
        for (int j = j0; j < j0 + 192; j++) {
            float uv = smu[j];
            float4 rv = *(const float4*)(rpb + (size_t)j * NT);
            a0 += uv * rv.x; a1 += uv * rv.y; a2 += uv * rv.z; a3 += uv * rv.w;
        }
        red[js][q][0] = a0; red[js][q][1] = a1; red[js][q][2] = a2; red[js][q][3] = a3;
    }
    __syncthreads();
    if (tid < 128) {
        int qq = tid >> 2, c = tid & 3;
        float rt = 0.f;
#pragma unroll
        for (int k = 0; k < 8; k++) rt += red[k][qq][c];
        int t = tq * 128 + qq * 4 + c;
        int ds = *dsp;
        float dsn = (float)(ds + 1);
        float bv = (bias_p[t] * dsn + z_p[t]) / (dsn + 1.0f);
        float zh = smu[NFEAT + t] + bv;
        float zb = g_zbm[(b * 16 + i) * NT + t];
        float ar = fabsf(rt) + 1.0f;
        float z2 = zh + rt / ar;
        g_G[i * NT + t] = (-0.03f / 16.0f) * sgnf(zb - z2) / (ar * ar);
        g_D[i * NT + t] = (-1.0f / 16.0f) * sgnf(zb - zh);
    }
}

// ===== N3: backD+ampgrad (blocks 0..511) | rg (blocks 512..895), 512 thr  [R4 body] =====
__global__ void k_N3(int b, const float* __restrict__ rp_p,
                     const float* __restrict__ are_p, const float* __restrict__ aim_p) {
    if (blockIdx.x < 512) {
        __shared__ float srz[NT];
        __shared__ float sD[16];
        __shared__ float stt[16];
        int t = blockIdx.x, tid = threadIdx.x;  // 512 threads
        srz[tid] = rp_p[(size_t)(NFEAT + t) * NT + tid];
        if (tid < 16) stt[tid] = g_tp2[b * 16 + tid];
        __syncthreads();
        int lane = tid & 31, w = tid >> 5;   // w = 0..15 = sample i
        float acc = 0.f;
#pragma unroll 4
        for (int tp = lane; tp < NT; tp += 32)
            acc += g_G[w * NT + tp] * srz[tp];
#pragma unroll
        for (int o = 16; o > 0; o >>= 1)
            acc += __shfl_down_sync(0xffffffffu, acc, o);
        if (lane == 0) sD[w] = g_D[w * NT + t] + acc;
        __syncthreads();
        if (tid < 32) {
            int f = tid;
            float are = are_p[f * NT + t], aim = aim_p[f * NT + t];
            float sre = 0.f, sim = 0.f, sf = 0.f;
#pragma unroll
            for (int i = 0; i < 16; i++) {
                float d = sD[i];
                float c = g_ct[i * 32 + f];
                float s = g_st[i * 32 + f];
                sre += d * c;
                sim -= d * s;
                sf += d * (-s * are - c * aim) * stt[i];
            }
            float aa = sqrtf(are * are + aim * aim);
            float reg = 0.01f / (2.0f * aa * sqrtf(aa));
            float agre = sre * RSQRTNF + are * reg;
            float agim = sim * RSQRTNF + aim * reg;
            g_agre[f * NT + t] = agre;
            g_agim[f * NT + t] = agim;
            atomicAdd(&g_fga[b][f], sf);
            float nrm = agre * agre + agim * agim;
#pragma unroll
            for (int o = 16; o > 0; o >>= 1)
                nrm += __shfl_down_sync(0xffffffffu, nrm, o);
            if (f == 0) atomicAdd(&g_nrm[b][0], nrm);
        }
    } else {
        __shared__ float su[16][4];
        __shared__ float swr[16];
        int j0 = (blockIdx.x - 512) * 4, tid = threadIdx.x;  // 512 threads
        if (tid < 64) {
            int i = tid >> 2, jj = tid & 3;
            int j = j0 + jj;
            float v = (j < NFEAT) ? g_ux[(b * 16 + i) * NFEAT + j]
                                  : g_uz[i * NT + (j - NFEAT)];
            su[i][jj] = v;
        }
        __syncthreads();
        float a0 = 0.f, a1 = 0.f, a2 = 0.f, a3 = 0.f;
#pragma unroll
        for (int i = 0; i < 16; i++) {
            float gv = g_G[i * NT + tid];
            a0 += su[i][0] * gv; a1 += su[i][1] * gv;
            a2 += su[i][2] * gv; a3 += su[i][3] * gv;
        }
        g_rg[(j0 + 0) * NT + tid] = a0;
        g_rg[(j0 + 1) * NT + tid] = a1;
        g_rg[(j0 + 2) * NT + tid] = a2;
        g_rg[(j0 + 3) * NT + tid] = a3;
        float loc = a0 * a0 + a1 * a1 + a2 * a2 + a3 * a3;
#pragma unroll
        for (int o = 16; o > 0; o >>= 1)
            loc += __shfl_down_sync(0xffffffffu, loc, o);
        if ((tid & 31) == 0) swr[tid >> 5] = loc;
        __syncthreads();
        if (tid < 16) {
            loc = swr[tid];
#pragma unroll
            for (int o = 8; o > 0; o >>= 1)
                loc += __shfl_down_sync(0x0000ffffu, loc, o);
            if (tid == 0) atomicAdd(&g_nrm[b][2], loc);
        }
    }
}

// ================= update: momentum + SGD, src -> out (no pre-copy needed) =================
__global__ void k_update(int b,
                         const float* __restrict__ rpg_s, const float* __restrict__ rp_s,
                         const float* __restrict__ agre_s, const float* __restrict__ are_s,
                         const float* __restrict__ agim_s, const float* __restrict__ aim_s,
                         const float* __restrict__ fg_s, const float* __restrict__ freq_s,
                         float* __restrict__ out) {
    const int NRP4 = NCAT * NT / 4;   // 196608
    const int NAMP4 = 32 * NT / 4;    // 4096
    int idx = blockIdx.x * 256 + threadIdx.x;
    float lr = g_lr;
    if (idx < NRP4) {
        float rn = sqrtf(g_nrm[b][2]) + 1.0f;
        float4 mo = ((const float4*)rpg_s)[idx];
        float4 gr = ((const float4*)g_rg)[idx];
        float4 pv = ((const float4*)rp_s)[idx];
        mo.x = mo.x * 0.85f + gr.x / rn;  pv.x -= mo.x * lr;
        mo.y = mo.y * 0.85f + gr.y / rn;  pv.y -= mo.y * lr;
        mo.z = mo.z * 0.85f + gr.z / rn;  pv.z -= mo.z * lr;
        mo.w = mo.w * 0.85f + gr.w / rn;  pv.w -= mo.w * lr;
        ((float4*)(out + OUT_RPG))[idx] = mo;
        ((float4*)(out + OUT_RP))[idx] = pv;
    } else if (idx < NRP4 + NAMP4) {
        int k = idx - NRP4;
        float an = sqrtf(g_nrm[b][0]) + 1.0f;
        float4 mo = ((const float4*)agre_s)[k];
        float4 gr = ((const float4*)g_agre)[k];
        float4 pv = ((const float4*)are_s)[k];
        mo.x = mo.x * 0.85f + gr.x / an;  pv.x -= mo.x * lr;
        mo.y = mo.y * 0.85f + gr.y / an;  pv.y -= mo.y * lr;
        mo.z = mo.z * 0.85f + gr.z / an;  pv.z -= mo.z * lr;
        mo.w = mo.w * 0.85f + gr.w / an;  pv.w -= mo.w * lr;
        ((float4*)(out + OUT_AGRE))[k] = mo;
        ((float4*)(out + OUT_ARE))[k] = pv;
        float4 mi = ((const float4*)agim_s)[k];
        float4 gi = ((const float4*)g_agim)[k];
        float4 pi = ((const float4*)aim_s)[k];
        mi.x = mi.x * 0.85f + gi.x / an;  pi.x -= mi.x * lr;
        mi.y = mi.y * 0.85f + gi.y / an;  pi.y -= mi.y * lr;
        mi.z = mi.z * 0.85f + gi.z / an;  pi.z -= mi.z * lr;
        mi.w = mi.w * 0.85f + gi.w / an;  pi.w -= mi.w * lr;
        ((float4*)(out + OUT_AGIM))[k] = mi;
        ((float4*)(out + OUT_AIM))[k] = pi;
    }
    if (blockIdx.x == 0 && threadIdx.x < 32) {
        int f = threadIdx.x;
        float fgv = (g_fga[b][f] * RSQRTNF) * g_dfr[b][f];
        float n = fgv * fgv;
#pragma unroll
        for (int o = 16; o > 0; o >>= 1)
            n += __shfl_xor_sync(0xffffffffu, n, o);
        float fn = sqrtf(n) + 1.0f;
        float m = fg_s[f] * 0.85f + fgv / fn;
        out[OUT_FG + f] = m;
        out[OUT_FREQ + f] = freq_s[f] - m * lr;
    }
}

extern "C" void kernel_launch(void* const* d_in, const int* in_sizes, int n_in,
                              void* d_out, int out_size) {
    const int*   t_p    = (const int*)d_in[0];
    const int*   ds_p   = (const int*)d_in[1];
    const int*   ts     = (const int*)d_in[2];
    const float* x      = (const float*)d_in[3];
    const float* z      = (const float*)d_in[4];
    const float* memory = (const float*)d_in[5];
    const int*   tmem   = (const int*)d_in[6];
    const float* fmem   = (const float*)d_in[7];
    const float* amp_re = (const float*)d_in[8];
    const float* amp_im = (const float*)d_in[9];
    const float* freq   = (const float*)d_in[10];
    const float* cfreq  = (const float*)d_in[11];
    const float* rp     = (const float*)d_in[12];
    const float* fmean  = (const float*)d_in[13];
    const float* bias   = (const float*)d_in[14];
    const float* agre   = (const float*)d_in[15];
    const float* agim   = (const float*)d_in[16];
    const float* fg     = (const float*)d_in[17];
    const float* rpg    = (const float*)d_in[18];
    float* out = (float*)d_out;

    static cudaStream_t s1 = 0;
    static cudaEvent_t e0 = 0, e1 = 0;
    if (!s1) {
        cudaStreamCreateWithFlags(&s1, cudaStreamNonBlocking);
        cudaEventCreateWithFlags(&e0, cudaEventDisableTiming);
        cudaEventCreateWithFlags(&e1, cudaEventDisableTiming);
    }

    // ---- fork: big copies on side stream ----
    cudaEventRecord(e0, 0);
    cudaStreamWaitEvent(s1, e0, 0);
    {
        const long long total4 = (long long)MEMSZ * NT / 4 + (long long)MEMSZ * NFEAT / 4 + MEMSZ / 4;
        int blocks = (int)((total4 + 255) / 256);
        k_bigcopy<<<blocks, 256, 0, s1>>>(memory, fmem, tmem, z, x, t_p, ds_p, out);
    }
    cudaEventRecord(e1, s1);

    // ---- main chain: 7 light nodes ----
    k_front<<<50, 512>>>(ts, memory, fmem, tmem, z, x, fmean, bias,
                         t_p, ds_p, freq, cfreq, amp_re, amp_im, out);

    // batch 0: everything reads INPUT params, update writes out
    k_N2<<<64, 256>>>(0, 0, freq, cfreq, amp_re, amp_im, rp, bias, z, ds_p);
    k_N3<<<896, 512>>>(0, rp, amp_re, amp_im);
    k_update<<<(NCAT * NT / 4 + 32 * NT / 4) / 256, 256>>>(0, rpg, rp, agre, amp_re,
                                                           agim, amp_im, fg, freq, out);

    // batch 1: params from out (updated), in place
    k_N2<<<64, 256>>>(1, 1, out + OUT_FREQ, cfreq, out + OUT_ARE, out + OUT_AIM,
                      out + OUT_RP, bias, z, ds_p);
    k_N3<<<896, 512>>>(1, out + OUT_RP, out + OUT_ARE, out + OUT_AIM);
    k_update<<<(NCAT * NT / 4 + 32 * NT / 4) / 256, 256>>>(1, out + OUT_RPG, out + OUT_RP,
                                                           out + OUT_AGRE, out + OUT_ARE,
                                                           out + OUT_AGIM, out + OUT_AIM,
                                                           out + OUT_FG, out + OUT_FREQ, out);

    // ---- join ----
    cudaStreamWaitEvent(0, e1, 0);
    (void)in_sizes; (void)n_in; (void)out_size;
}

// round 8
// speedup vs baseline: 1.1929x; 1.1200x over previous
#include <cuda_runtime.h>
#include <math.h>

#define NT 512
#define NFEAT 1024
#define NCAT 1536
#define MEMSZ 16384
#define RSQRTNF 0.17677669529663689f

// ---- output layout (float element offsets) ----
#define OUT_MEM    0
#define OUT_TMEM   8388608
#define OUT_FMEM   8404992
#define OUT_ARE    25182208
#define OUT_AIM    25198592
#define OUT_FREQ   25214976
#define OUT_RP     25215008
#define OUT_BIAS   26001440
#define OUT_FMEAN  26001952
#define OUT_AGRE   26002976
#define OUT_AGIM   26019360
#define OUT_FG     26035744
#define OUT_RPG    26035776

// ---- scratch ----
__device__ __align__(16) float g_ux[32 * NFEAT];   // x-part of u
__device__ __align__(16) float g_uz[16 * NT];      // z-part of u, current batch
__device__ __align__(16) float g_G[16 * NT];
__device__ __align__(16) float g_D[16 * NT];
__device__ __align__(16) float g_ct[16 * 32];
__device__ __align__(16) float g_st[16 * 32];
__device__ __align__(16) float g_tp2[32];
__device__ __align__(16) float g_dfr[2][32];
__device__ __align__(16) float g_agre[32 * NT];
__device__ __align__(16) float g_agim[32 * NT];
__device__ __align__(16) float g_fga[2][32];
__device__ __align__(16) float g_rg[NCAT * NT];
__device__ float g_nrm[2][4];
__device__ float g_lr;

__device__ __forceinline__ float sgnf(float v) {
    return (v > 0.f) ? 1.f : ((v < 0.f) ? -1.f : 0.f);
}

__device__ __forceinline__ void trig_one(float fq_f, float cfv, float tt,
                                         float* cv, float* sv, float* dfr) {
    double fq = (double)fq_f;
    double th = tanh(fq);
    double w = (double)cfv + 2.0 * th;
    double sg = 1.0 / (1.0 + exp(-w));
    double ph = (double)tt * (sg * 0.5);
    *cv = (float)cos(ph);
    *sv = (float)sin(ph);
    *dfr = (float)(0.5 * sg * (1.0 - sg) * 2.0 * (1.0 - th * th));
}

// ================= side stream =================
__device__ __forceinline__ void copy_one(long long u, int ds,
        const float* __restrict__ memory, const float* __restrict__ fmem,
        const int* __restrict__ tmem, const float* __restrict__ z,
        const float* __restrict__ x, const int* __restrict__ tp,
        float* __restrict__ out) {
    const long long N1 = (long long)MEMSZ * NT / 4;
    const long long N2c = (long long)MEMSZ * NFEAT / 4;
    if (u < N1) {
        int k = (int)u;
        int row = (k * 4) >> 9;
        float4 v;
        if (row == ds) v = *(const float4*)(z + ((k * 4) & 511));
        else           v = ((const float4*)memory)[k];
        ((float4*)(out + OUT_MEM))[k] = v;
    } else if (u < N1 + N2c) {
        int k = (int)(u - N1);
        int row = (k * 4) >> 10;
        float4 v;
        if (row == ds) v = *(const float4*)(x + ((k * 4) & 1023));
        else           v = ((const float4*)fmem)[k];
        ((float4*)(out + OUT_FMEM))[k] = v;
    } else {
        int k = (int)(u - N1 - N2c);
        int4 iv = ((const int4*)tmem)[k];
        float4 f = make_float4((float)iv.x, (float)iv.y, (float)iv.z, (float)iv.w);
        if ((ds >> 2) == k) ((float*)&f)[ds & 3] = (float)(*tp);
        ((float4*)(out + OUT_TMEM))[k] = f;
    }
}

// grid-stride, SM-friendly (2 blocks/SM), 4-way MLP
__global__ void k_bigcopy(const float* __restrict__ memory, const float* __restrict__ fmem,
                          const int* __restrict__ tmem,
                          const float* __restrict__ z, const float* __restrict__ x,
                          const int* __restrict__ tp, const int* __restrict__ dsp,
                          float* __restrict__ out) {
    const long long total = (long long)MEMSZ * NT / 4 + (long long)MEMSZ * NFEAT / 4 + MEMSZ / 4;
    long long stride = (long long)gridDim.x * blockDim.x;
    long long u0 = (long long)blockIdx.x * blockDim.x + threadIdx.x;
    int ds = *dsp;
    for (long long u = u0; u < total; u += 4 * stride) {
        copy_one(u, ds, memory, fmem, tmem, z, x, tp, out);
        if (u + stride < total)     copy_one(u + stride, ds, memory, fmem, tmem, z, x, tp, out);
        if (u + 2 * stride < total) copy_one(u + 2 * stride, ds, memory, fmem, tmem, z, x, tp, out);
        if (u + 3 * stride < total) copy_one(u + 3 * stride, ds, memory, fmem, tmem, z, x, tp, out);
    }
}

// bias / fmean outputs (independent of the optimizer chain)
__global__ void k_misc(const float* __restrict__ bias, const float* __restrict__ fmean,
                       const float* __restrict__ z, const float* __restrict__ x,
                       const int* __restrict__ dsp, float* __restrict__ out) {
    int ds = *dsp;
    float dsn = (float)(ds + 1);
    int u = blockIdx.x * 512 + threadIdx.x;
    if (u < NT) out[OUT_BIAS + u] = (bias[u] * dsn + z[u]) / (dsn + 1.0f);
    if (u < NFEAT) out[OUT_FMEAN + u] = (fmean[u] * dsn + x[u]) / (dsn + 1.0f);
}

// ================= N2: self-gathering eval + r GEMM + G/D  (64 blocks x 256) =================
__global__ void k_N2(int b,
                     const float* __restrict__ freq_p, const float* __restrict__ cf,
                     const float* __restrict__ are_p, const float* __restrict__ aim_p,
                     const float* __restrict__ rp_p,
                     const float* __restrict__ bias_in, const float* __restrict__ z_in,
                     const float* __restrict__ memory, const float* __restrict__ fmem,
                     const int* __restrict__ tmem, const int* __restrict__ ts,
                     const int* __restrict__ tp, const int* __restrict__ dsp,
                     const float* __restrict__ fmean, const float* __restrict__ x) {
    __shared__ float smu[NCAT];
    __shared__ float red[8][32][4];
    __shared__ float sc[32], ss[32];
    int tid = threadIdx.x;
    int i = blockIdx.x >> 2, tq = blockIdx.x & 3;
    int ds = *dsp;
    float dsn = (float)(ds + 1);
    int idx = ts[b * 16 + i];

    // housekeeping (block 0 only): zero accumulators for this batch, lr
    if (blockIdx.x == 0) {
        if (tid >= 64 && tid < 68) g_nrm[b][tid - 64] = 0.f;
        if (tid >= 96 && tid < 128) g_fga[b][tid - 96] = 0.f;
        if (tid == 68 && b == 0) g_lr = (float)pow(0.977, (double)(ds + 1));
    }

    // gather x-part of u straight from inputs
    for (int j = tid; j < NFEAT; j += 256) {
        float xv = (idx == ds) ? x[j] : fmem[idx * NFEAT + j];
        float fm = (fmean[j] * dsn + x[j]) / (dsn + 1.0f);
        smu[j] = xv - fm;
        if (tq == 0) g_ux[(b * 16 + i) * NFEAT + j] = xv - fm;
    }
    float tv = (idx == ds) ? (float)(*tp) : (float)tmem[idx];
    float tt = 6.2831853071795864769f * tv;
    if (tq == 0 && tid == 0) g_tp2[b * 16 + i] = tt;

    if (tid < 32) {
        float cv, sv, dfr;
        trig_one(freq_p[tid], cf[tid], tt, &cv, &sv, &dfr);
        sc[tid] = cv; ss[tid] = sv;
        if (tq == 0) {
            g_ct[i * 32 + tid] = cv;
            g_st[i * 32 + tid] = sv;
        }
        if (blockIdx.x == 0) g_dfr[b][tid] = dfr;
    }
    __syncthreads();

    // z-part of u (z_hat - bias)
    for (int t2 = tid; t2 < NT; t2 += 256) {
        float acc = 0.f;
#pragma unroll
        for (int f = 0; f < 32; f++)
            acc += sc[f] * are_p[f * NT + t2] - ss[f] * aim_p[f * NT + t2];
        acc *= RSQRTNF;
        smu[NFEAT + t2] = acc;
        if (tq == 0) g_uz[i * NT + t2] = acc;
    }
    __syncthreads();

    // r = u @ rp for this sample, t-quarter tq
    {
        int q = tid & 31, js = tid >> 5;
        int tb = tq * 128 + q * 4;
        float a0 = 0.f, a1 = 0.f, a2 = 0.f, a3 = 0.f;
        const float* rpb = rp_p + tb;
        int j0 = js * 192;
#pragma unroll 8
        for (int j = j0; j < j0 + 192; j++) {
            float uv = smu[j];
            float4 rv = *(const float4*)(rpb + (size_t)j * NT);
            a0 += uv * rv.x; a1 += uv * rv.y; a2 += uv * rv.z; a3 += uv * rv.w;
        }
        red[js][q][0] = a0; red[js][q][1] = a1; red[js][q][2] = a2; red[js][q][3] = a3;
    }
    __syncthreads();
    if (tid < 128) {
        int qq = tid >> 2, c = tid & 3;
        float rt = 0.f;
#pragma unroll
        for (int k = 0; k < 8; k++) rt += red[k][qq][c];
        int t = tq * 128 + qq * 4 + c;
        float bv = (bias_in[t] * dsn + z_in[t]) / (dsn + 1.0f);
        float zh = smu[NFEAT + t] + bv;
        float zb = (idx == ds) ? z_in[t] : memory[idx * NT + t];
        float ar = fabsf(rt) + 1.0f;
        float z2 = zh + rt / ar;
        g_G[i * NT + t] = (-0.03f / 16.0f) * sgnf(zb - z2) / (ar * ar);
        g_D[i * NT + t] = (-1.0f / 16.0f) * sgnf(zb - zh);
    }
}

// ===== N3: backD+ampgrad (blocks 0..511) | rg (blocks 512..895), 512 thr  [R4 body] =====
__global__ void k_N3(int b, const float* __restrict__ rp_p,
                     const float* __restrict__ are_p, const float* __restrict__ aim_p) {
    if (blockIdx.x < 512) {
        __shared__ float srz[NT];
        __shared__ float sD[16];
        __shared__ float stt[16];
        int t = blockIdx.x, tid = threadIdx.x;
        srz[tid] = rp_p[(size_t)(NFEAT + t) * NT + tid];
        if (tid < 16) stt[tid] = g_tp2[b * 16 + tid];
        __syncthreads();
        int lane = tid & 31, w = tid >> 5;
        float acc = 0.f;
#pragma unroll 4
        for (int tp = lane; tp < NT; tp += 32)
            acc += g_G[w * NT + tp] * srz[tp];
#pragma unroll
        for (int o = 16; o > 0; o >>= 1)
            acc += __shfl_down_sync(0xffffffffu, acc, o);
        if (lane == 0) sD[w] = g_D[w * NT + t] + acc;
        __syncthreads();
        if (tid < 32) {
            int f = tid;
            float are = are_p[f * NT + t], aim = aim_p[f * NT + t];
            float sre = 0.f, sim = 0.f, sf = 0.f;
#pragma unroll
            for (int i = 0; i < 16; i++) {
                float d = sD[i];
                float c = g_ct[i * 32 + f];
                float s = g_st[i * 32 + f];
                sre += d * c;
                sim -= d * s;
                sf += d * (-s * are - c * aim) * stt[i];
            }
            float aa = sqrtf(are * are + aim * aim);
            float reg = 0.01f / (2.0f * aa * sqrtf(aa));
            float agre = sre * RSQRTNF + are * reg;
            float agim = sim * RSQRTNF + aim * reg;
            g_agre[f * NT + t] = agre;
            g_agim[f * NT + t] = agim;
            atomicAdd(&g_fga[b][f], sf);
            float nrm = agre * agre + agim * agim;
#pragma unroll
            for (int o = 16; o > 0; o >>= 1)
                nrm += __shfl_down_sync(0xffffffffu, nrm, o);
            if (f == 0) atomicAdd(&g_nrm[b][0], nrm);
        }
    } else {
        __shared__ float su[16][4];
        __shared__ float swr[16];
        int j0 = (blockIdx.x - 512) * 4, tid = threadIdx.x;
        if (tid < 64) {
            int i = tid >> 2, jj = tid & 3;
            int j = j0 + jj;
            float v = (j < NFEAT) ? g_ux[(b * 16 + i) * NFEAT + j]
                                  : g_uz[i * NT + (j - NFEAT)];
            su[i][jj] = v;
        }
        __syncthreads();
        float a0 = 0.f, a1 = 0.f, a2 = 0.f, a3 = 0.f;
#pragma unroll
        for (int i = 0; i < 16; i++) {
            float gv = g_G[i * NT + tid];
            a0 += su[i][0] * gv; a1 += su[i][1] * gv;
            a2 += su[i][2] * gv; a3 += su[i][3] * gv;
        }
        g_rg[(j0 + 0) * NT + tid] = a0;
        g_rg[(j0 + 1) * NT + tid] = a1;
        g_rg[(j0 + 2) * NT + tid] = a2;
        g_rg[(j0 + 3) * NT + tid] = a3;
        float loc = a0 * a0 + a1 * a1 + a2 * a2 + a3 * a3;
#pragma unroll
        for (int o = 16; o > 0; o >>= 1)
            loc += __shfl_down_sync(0xffffffffu, loc, o);
        if ((tid & 31) == 0) swr[tid >> 5] = loc;
        __syncthreads();
        if (tid < 16) {
            loc = swr[tid];
#pragma unroll
            for (int o = 8; o > 0; o >>= 1)
                loc += __shfl_down_sync(0x0000ffffu, loc, o);
            if (tid == 0) atomicAdd(&g_nrm[b][2], loc);
        }
    }
}

// ================= update: momentum + SGD, src -> out =================
__global__ void k_update(int b,
                         const float* __restrict__ rpg_s, const float* __restrict__ rp_s,
                         const float* __restrict__ agre_s, const float* __restrict__ are_s,
                         const float* __restrict__ agim_s, const float* __restrict__ aim_s,
                         const float* __restrict__ fg_s, const float* __restrict__ freq_s,
                         float* __restrict__ out) {
    const int NRP4 = NCAT * NT / 4;
    const int NAMP4 = 32 * NT / 4;
    int idx = blockIdx.x * 256 + threadIdx.x;
    float lr = g_lr;
    if (idx < NRP4) {
        float rn = sqrtf(g_nrm[b][2]) + 1.0f;
        float4 mo = ((const float4*)rpg_s)[idx];
        float4 gr = ((const float4*)g_rg)[idx];
        float4 pv = ((const float4*)rp_s)[idx];
        mo.x = mo.x * 0.85f + gr.x / rn;  pv.x -= mo.x * lr;
        mo.y = mo.y * 0.85f + gr.y / rn;  pv.y -= mo.y * lr;
        mo.z = mo.z * 0.85f + gr.z / rn;  pv.z -= mo.z * lr;
        mo.w = mo.w * 0.85f + gr.w / rn;  pv.w -= mo.w * lr;
        ((float4*)(out + OUT_RPG))[idx] = mo;
        ((float4*)(out + OUT_RP))[idx] = pv;
    } else if (idx < NRP4 + NAMP4) {
        int k = idx - NRP4;
        float an = sqrtf(g_nrm[b][0]) + 1.0f;
        float4 mo = ((const float4*)agre_s)[k];
        float4 gr = ((const float4*)g_agre)[k];
        float4 pv = ((const float4*)are_s)[k];
        mo.x = mo.x * 0.85f + gr.x / an;  pv.x -= mo.x * lr;
        mo.y = mo.y * 0.85f + gr.y / an;  pv.y -= mo.y * lr;
        mo.z = mo.z * 0.85f + gr.z / an;  pv.z -= mo.z * lr;
        mo.w = mo.w * 0.85f + gr.w / an;  pv.w -= mo.w * lr;
        ((float4*)(out + OUT_AGRE))[k] = mo;
        ((float4*)(out + OUT_ARE))[k] = pv;
        float4 mi = ((const float4*)agim_s)[k];
        float4 gi = ((const float4*)g_agim)[k];
        float4 pi = ((const float4*)aim_s)[k];
        mi.x = mi.x * 0.85f + gi.x / an;  pi.x -= mi.x * lr;
        mi.y = mi.y * 0.85f + gi.y / an;  pi.y -= mi.y * lr;
        mi.z = mi.z * 0.85f + gi.z / an;  pi.z -= mi.z * lr;
        mi.w = mi.w * 0.85f + gi.w / an;  pi.w -= mi.w * lr;
        ((float4*)(out + OUT_AGIM))[k] = mi;
        ((float4*)(out + OUT_AIM))[k] = pi;
    }
    if (blockIdx.x == 0 && threadIdx.x < 32) {
        int f = threadIdx.x;
        float fgv = (g_fga[b][f] * RSQRTNF) * g_dfr[b][f];
        float n = fgv * fgv;
#pragma unroll
        for (int o = 16; o > 0; o >>= 1)
            n += __shfl_xor_sync(0xffffffffu, n, o);
        float fn = sqrtf(n) + 1.0f;
        float m = fg_s[f] * 0.85f + fgv / fn;
        out[OUT_FG + f] = m;
        out[OUT_FREQ + f] = freq_s[f] - m * lr;
    }
}

extern "C" void kernel_launch(void* const* d_in, const int* in_sizes, int n_in,
                              void* d_out, int out_size) {
    const int*   t_p    = (const int*)d_in[0];
    const int*   ds_p   = (const int*)d_in[1];
    const int*   ts     = (const int*)d_in[2];
    const float* x      = (const float*)d_in[3];
    const float* z      = (const float*)d_in[4];
    const float* memory = (const float*)d_in[5];
    const int*   tmem   = (const int*)d_in[6];
    const float* fmem   = (const float*)d_in[7];
    const float* amp_re = (const float*)d_in[8];
    const float* amp_im = (const float*)d_in[9];
    const float* freq   = (const float*)d_in[10];
    const float* cfreq  = (const float*)d_in[11];
    const float* rp     = (const float*)d_in[12];
    const float* fmean  = (const float*)d_in[13];
    const float* bias   = (const float*)d_in[14];
    const float* agre   = (const float*)d_in[15];
    const float* agim   = (const float*)d_in[16];
    const float* fg     = (const float*)d_in[17];
    const float* rpg    = (const float*)d_in[18];
    float* out = (float*)d_out;

    static cudaStream_t s1 = 0;
    static cudaEvent_t e0 = 0, e1 = 0;
    if (!s1) {
        cudaStreamCreateWithFlags(&s1, cudaStreamNonBlocking);
        cudaEventCreateWithFlags(&e0, cudaEventDisableTiming);
        cudaEventCreateWithFlags(&e1, cudaEventDisableTiming);
    }

    // ---- fork: misc + throttled big copy on side stream ----
    cudaEventRecord(e0, 0);
    cudaStreamWaitEvent(s1, e0, 0);
    k_misc<<<2, 512, 0, s1>>>(bias, fmean, z, x, ds_p, out);
    k_bigcopy<<<296, 256, 0, s1>>>(memory, fmem, tmem, z, x, t_p, ds_p, out);
    cudaEventRecord(e1, s1);

    // ---- main chain: 6 nodes ----
    // batch 0: params from inputs
    k_N2<<<64, 256>>>(0, freq, cfreq, amp_re, amp_im, rp, bias, z,
                      memory, fmem, tmem, ts, t_p, ds_p, fmean, x);
    k_N3<<<896, 512>>>(0, rp, amp_re, amp_im);
    k_update<<<(NCAT * NT / 4 + 32 * NT / 4) / 256, 256>>>(0, rpg, rp, agre, amp_re,
                                                           agim, amp_im, fg, freq, out);
    // batch 1: params from out (updated), in place
    k_N2<<<64, 256>>>(1, out + OUT_FREQ, cfreq, out + OUT_ARE, out + OUT_AIM,
                      out + OUT_RP, bias, z, memory, fmem, tmem, ts, t_p, ds_p, fmean, x);
    k_N3<<<896, 512>>>(1, out + OUT_RP, out + OUT_ARE, out + OUT_AIM);
    k_update<<<(NCAT * NT / 4 + 32 * NT / 4) / 256, 256>>>(1, out + OUT_RPG, out + OUT_RP,
                                                           out + OUT_AGRE, out + OUT_ARE,
                                                           out + OUT_AGIM, out + OUT_AIM,
                                                           out + OUT_FG, out + OUT_FREQ, out);

    // ---- join ----
    cudaStreamWaitEvent(0, e1, 0);
    (void)in_sizes; (void)n_in; (void)out_size;
}